// round 10
// baseline (speedup 1.0000x reference)
#include <cuda_runtime.h>
#include <cstdint>
#include <math.h>

// NaiveFourierKANLayer, warp-specialized fp16 MMA, 4-stage pipeline:
//   y[32768,256] = A[32768,4096] @ W[4096,256] + bias
// Warps 0-7 consume (LDSM+HMMA only); warps 8-15 produce (A-gen + W cp.async).
// W(i) is kicked at iteration i-2, so its global->smem latency is hidden by
// two full pipeline iterations; wait_group 2 certifies completion without
// blocking on the in-flight groups.

#define NROWS   32768
#define INDIM   64
#define OUTDIM  256

// ---------- helpers ----------
__device__ __forceinline__ uint32_t smem_u32(const void* p) {
    uint32_t a;
    asm("{ .reg .u64 t; cvta.to.shared.u64 t, %1; cvt.u32.u64 %0, t; }" : "=r"(a) : "l"(p));
    return a;
}
__device__ __forceinline__ uint32_t pack_f16(float e0, float e1) {   // low half = e0
    uint32_t r;
    asm("cvt.rn.f16x2.f32 %0, %1, %2;" : "=r"(r) : "f"(e1), "f"(e0));
    return r;
}
__device__ __forceinline__ uint32_t swz(uint32_t off) { return off ^ ((off >> 3) & 0x70); }

__device__ __forceinline__ void cpa16(uint32_t dst, const void* src) {
    asm volatile("cp.async.cg.shared.global [%0], [%1], 16;" :: "r"(dst), "l"(src) : "memory");
}
#define CP_COMMIT() asm volatile("cp.async.commit_group;" ::: "memory")
#define CP_WAIT(n)  asm volatile("cp.async.wait_group %0;" :: "n"(n) : "memory")

// named split barriers, whole-CTA count (512)
#define BAR_SYNC(id)   asm volatile("bar.sync %0, 512;"   :: "r"(id) : "memory")
#define BAR_ARRIVE(id) asm volatile("bar.arrive %0, 512;" :: "r"(id) : "memory")
// FULL[s] = 1+s (producer arrives, consumer syncs), s = 0..3
// EMPTY[s] = 5+s (consumer arrives, producer syncs)

__device__ __forceinline__ void ldsm4(uint32_t* r, uint32_t addr) {
    asm volatile("ldmatrix.sync.aligned.m8n8.x4.shared.b16 {%0,%1,%2,%3}, [%4];"
                 : "=r"(r[0]), "=r"(r[1]), "=r"(r[2]), "=r"(r[3]) : "r"(addr));
}
__device__ __forceinline__ void mma_f16(float* d, const uint32_t* a, uint32_t b0, uint32_t b1) {
    asm volatile("mma.sync.aligned.m16n8k16.row.col.f32.f16.f16.f32 "
                 "{%0,%1,%2,%3},{%4,%5,%6,%7},{%8,%9},{%0,%1,%2,%3};"
                 : "+f"(d[0]), "+f"(d[1]), "+f"(d[2]), "+f"(d[3])
                 : "r"(a[0]), "r"(a[1]), "r"(a[2]), "r"(a[3]), "r"(b0), "r"(b1));
}

// ---------- pre-swizzled fp16 W tiles ----------
// g_wt[i][slab(o>>7)][ swz((o&127)*128 + f*2) ] : 32KB per i (2 slabs x 16KB)
__device__ __align__(1024) unsigned char g_wt[64 * 32768];

__global__ void kan_wprep(const float* __restrict__ w) {
    const int i = blockIdx.x;
    const int o = threadIdx.x;
    const float* pc = w + ((size_t)(0 * 256 + o) * 64 + i) * 32;
    const float* ps = w + ((size_t)(1 * 256 + o) * 64 + i) * 32;
    unsigned char* dst = g_wt + (size_t)i * 32768 + (o >> 7) * 16384;
    const uint32_t rowb = (uint32_t)(o & 127) * 128;

    #pragma unroll
    for (int half = 0; half < 2; ++half) {
        const float* src = half ? ps : pc;
        #pragma unroll
        for (int g = 0; g < 4; ++g) {
            float4 v0 = *(const float4*)(src + g * 8);
            float4 v1 = *(const float4*)(src + g * 8 + 4);
            uint32_t h[4];
            h[0] = pack_f16(v0.x, v0.y); h[1] = pack_f16(v0.z, v0.w);
            h[2] = pack_f16(v1.x, v1.y); h[3] = pack_f16(v1.z, v1.w);
            uint32_t off = swz(rowb + half * 64 + g * 16);
            *(uint4*)(dst + off) = make_uint4(h[0], h[1], h[2], h[3]);
        }
    }
}

// ---------- main kernel ----------
// SMEM (128KB): A stage s @ s*16384 (0..64KB); W stage s @ 65536 + s*16384
#define SA(s)    ((uint32_t)(s) * 16384u)
#define SW(s)    (65536u + (uint32_t)(s) * 16384u)
#define SMEM_SZ  131072

__global__ __launch_bounds__(512, 1)
void kan_mma(const float* __restrict__ x, const float* __restrict__ bias,
             float* __restrict__ out) {
    extern __shared__ __align__(1024) unsigned char sm[];
    const uint32_t sb = smem_u32(sm);
    const int t = threadIdx.x, lane = t & 31, wid = t >> 5;
    const int row0 = blockIdx.x * 128, col0 = blockIdx.y * 128;

    if (wid >= 8) {
        // ================= PRODUCERS (warps 8-15, 256 threads) =================
        const int pt = t - 256;
        const int ar = pt & 127;           // row
        const int ah = pt >> 7;            // 0 -> k=1..16, 1 -> k=17..32
        const uint32_t genrow = (uint32_t)ar * 128;
        const uint32_t genxm  = ((uint32_t)ar & 7) << 4;
        const unsigned char* wslab = g_wt + (size_t)(col0 >> 7) * 16384;
        const float* xrow = x + (size_t)(row0 + ar) * INDIM;

        // kick cp.async of W(ii) into stage ii&3 (16KB, 4x16B per thread)
        #define KICK_W(ii) do {                                                  \
            const unsigned char* ws_ = wslab + (size_t)(ii) * 32768;             \
            const uint32_t wd_ = sb + SW((ii) & 3);                              \
            _Pragma("unroll")                                                    \
            for (int j = 0; j < 4; ++j) {                                        \
                uint32_t off_ = ((uint32_t)pt + j * 256u) * 16u;                 \
                cpa16(wd_ + off_, ws_ + off_);                                   \
            }                                                                    \
            CP_COMMIT();                                                         \
        } while (0)

        KICK_W(0);
        KICK_W(1);

        #pragma unroll 1
        for (int i = 0; i < INDIM; ++i) {
            const int s = i & 3;

            // kick W two iterations ahead (stage (i+2)&3 freed by consumer i-2)
            if (i + 2 < INDIM) {
                if (i + 2 >= 4) BAR_SYNC(5 + ((i + 2) & 3));
                KICK_W(i + 2);
            }

            // A(i) -> stage s (stage known free: EMPTY synced when W(i) kicked)
            float xv = __ldg(xrow + i);
            float c1, s1, ck, sk;
            __sincosf(xv, &s1, &c1);
            if (ah) { float a17 = 17.0f * xv; sk = __sinf(a17); ck = __cosf(a17); }
            else    { ck = c1; sk = s1; }
            uint32_t chv[8], shv[8];
            #pragma unroll
            for (int p = 0; p < 8; ++p) {
                float cc0 = ck, ss0 = sk;
                float cA = fmaf(ck, c1, -(sk * s1));
                float sA = fmaf(sk, c1, ck * s1);
                chv[p] = pack_f16(cc0, cA);
                shv[p] = pack_f16(ss0, sA);
                ck = fmaf(cA, c1, -(sA * s1)); sk = fmaf(sA, c1, cA * s1);
            }
            const uint32_t ab = SA(s);
            #pragma unroll
            for (int g = 0; g < 2; ++g) {
                uint32_t cb = (uint32_t)ah * 32 + g * 16;
                uint32_t oc = genrow + (cb ^ genxm);
                uint32_t os = genrow + ((cb + 64u) ^ genxm);
                *(uint4*)(sm + ab + oc) = make_uint4(chv[4*g], chv[4*g+1], chv[4*g+2], chv[4*g+3]);
                *(uint4*)(sm + ab + os) = make_uint4(shv[4*g], shv[4*g+1], shv[4*g+2], shv[4*g+3]);
            }

            // certify W(i) landed: newest (up to) 2 groups may stay in flight
            if (i < INDIM - 2)      { CP_WAIT(2); }
            else if (i == INDIM - 2){ CP_WAIT(1); }
            else                    { CP_WAIT(0); }

            BAR_ARRIVE(1 + s);                     // publish FULL(s)
        }
        #undef KICK_W
        return;
    }

    // ================= CONSUMERS (warps 0-7) =================
    const int wm = wid & 3, wn = wid >> 2;             // 4 x 2 warp grid
    const int m0 = wm * 32, n0 = wn * 64;
    const int a_r   = m0 + (lane & 15);
    const uint32_t a_kadd = (lane & 16) ? 16u : 0u;
    const uint32_t a_xm   = ((uint32_t)a_r & 7) << 4;
    const int b_r   = n0 + (lane & 7) + ((lane & 16) ? 8 : 0);
    const uint32_t b_kadd = (lane & 8) ? 16u : 0u;
    const uint32_t b_xm   = ((uint32_t)b_r & 7) << 4;

    float acc[2][8][4];
    #pragma unroll
    for (int mt = 0; mt < 2; ++mt)
        #pragma unroll
        for (int nt = 0; nt < 8; ++nt)
            #pragma unroll
            for (int e = 0; e < 4; ++e) acc[mt][nt][e] = 0.0f;

    #pragma unroll 1
    for (int i = 0; i < INDIM; ++i) {
        const int s = i & 3;
        BAR_SYNC(1 + s);                               // wait FULL(s)
        const uint32_t Ab = sb + SA(s);
        const uint32_t Wb = sb + SW(s);
        #pragma unroll
        for (int ks = 0; ks < 4; ++ks) {
            const uint32_t kb = ks * 32;
            const uint32_t acol = (kb + a_kadd) ^ a_xm;
            const uint32_t bcol = (kb + b_kadd) ^ b_xm;
            uint32_t ahr[2][4];
            #pragma unroll
            for (int mt = 0; mt < 2; ++mt)
                ldsm4(ahr[mt], Ab + (uint32_t)(a_r + mt * 16) * 128 + acol);
            #pragma unroll
            for (int pr = 0; pr < 4; ++pr) {
                uint32_t bh[4];
                ldsm4(bh, Wb + (uint32_t)(b_r + pr * 16) * 128 + bcol);
                #pragma unroll
                for (int mt = 0; mt < 2; ++mt)
                    #pragma unroll
                    for (int h = 0; h < 2; ++h)
                        mma_f16(acc[mt][pr * 2 + h], ahr[mt], bh[h * 2], bh[h * 2 + 1]);
            }
        }
        BAR_ARRIVE(5 + s);                             // release EMPTY(s)
    }

    // ---------- epilogue ----------
    const int grp = lane >> 2, tig = lane & 3;
    #pragma unroll
    for (int nt = 0; nt < 8; ++nt) {
        const int cg = col0 + n0 + nt * 8 + 2 * tig;
        const float2 bs = *(const float2*)&bias[cg];
        #pragma unroll
        for (int mt = 0; mt < 2; ++mt) {
            const int rg = row0 + m0 + mt * 16 + grp;
            float2 v0 = make_float2(acc[mt][nt][0] + bs.x, acc[mt][nt][1] + bs.y);
            float2 v1 = make_float2(acc[mt][nt][2] + bs.x, acc[mt][nt][3] + bs.y);
            *(float2*)&out[(size_t)rg * OUTDIM + cg]       = v0;
            *(float2*)&out[(size_t)(rg + 8) * OUTDIM + cg] = v1;
        }
    }
}

extern "C" void kernel_launch(void* const* d_in, const int* in_sizes, int n_in,
                              void* d_out, int out_size) {
    const float* x    = (const float*)d_in[0];   // [32768][64]
    const float* w    = (const float*)d_in[1];   // [2][256][64][32]
    const float* bias = (const float*)d_in[2];   // [1][256]
    float* out        = (float*)d_out;           // [32768][256]

    cudaFuncSetAttribute(kan_mma, cudaFuncAttributeMaxDynamicSharedMemorySize, SMEM_SZ);

    kan_wprep<<<64, 256>>>(w);
    dim3 grid(NROWS / 128, OUTDIM / 128);        // (256, 2)
    kan_mma<<<grid, 512, SMEM_SZ>>>(x, bias, out);
}

// round 11
// speedup vs baseline: 1.2034x; 1.2034x over previous
#include <cuda_runtime.h>
#include <cstdint>
#include <math.h>

// NaiveFourierKANLayer, warp-specialized fp16 MMA:
//   y[32768,256] = A[32768,4096] @ W[4096,256] + bias
// 384 threads/CTA: warps 0-7 consumers (LDSM+HMMA, double-buffered fragments),
// warps 8-11 producers (full-row A-gen + W cp.async). 2-stage smem pipeline.
// 384 threads => per-thread reg cap ~168, letting ptxas pipeline LDSM vs MMA.

#define NROWS   32768
#define INDIM   64
#define OUTDIM  256

// ---------- helpers ----------
__device__ __forceinline__ uint32_t smem_u32(const void* p) {
    uint32_t a;
    asm("{ .reg .u64 t; cvta.to.shared.u64 t, %1; cvt.u32.u64 %0, t; }" : "=r"(a) : "l"(p));
    return a;
}
__device__ __forceinline__ uint32_t pack_f16(float e0, float e1) {   // low half = e0
    uint32_t r;
    asm("cvt.rn.f16x2.f32 %0, %1, %2;" : "=r"(r) : "f"(e1), "f"(e0));
    return r;
}
__device__ __forceinline__ uint32_t swz(uint32_t off) { return off ^ ((off >> 3) & 0x70); }

__device__ __forceinline__ void cpa16(uint32_t dst, const void* src) {
    asm volatile("cp.async.cg.shared.global [%0], [%1], 16;" :: "r"(dst), "l"(src) : "memory");
}
#define CP_COMMIT() asm volatile("cp.async.commit_group;" ::: "memory")
#define CP_WAIT0()  asm volatile("cp.async.wait_group 0;" ::: "memory")

// named split barriers, whole-CTA count (384)
#define BAR_SYNC(id)   asm volatile("bar.sync %0, 384;"   :: "r"(id) : "memory")
#define BAR_ARRIVE(id) asm volatile("bar.arrive %0, 384;" :: "r"(id) : "memory")
// FULL[b] = 1+b (producers arrive, consumers sync)
// EMPTY[b] = 3+b (consumers arrive, producers sync)

__device__ __forceinline__ void ldsm4(uint32_t* r, uint32_t addr) {
    asm volatile("ldmatrix.sync.aligned.m8n8.x4.shared.b16 {%0,%1,%2,%3}, [%4];"
                 : "=r"(r[0]), "=r"(r[1]), "=r"(r[2]), "=r"(r[3]) : "r"(addr));
}
__device__ __forceinline__ void mma_f16(float* d, const uint32_t* a, uint32_t b0, uint32_t b1) {
    asm volatile("mma.sync.aligned.m16n8k16.row.col.f32.f16.f16.f32 "
                 "{%0,%1,%2,%3},{%4,%5,%6,%7},{%8,%9},{%0,%1,%2,%3};"
                 : "+f"(d[0]), "+f"(d[1]), "+f"(d[2]), "+f"(d[3])
                 : "r"(a[0]), "r"(a[1]), "r"(a[2]), "r"(a[3]), "r"(b0), "r"(b1));
}

// ---------- pre-swizzled fp16 W tiles ----------
// g_wt[i][slab(o>>7)][ swz((o&127)*128 + f*2) ] : 32KB per i (2 slabs x 16KB)
__device__ __align__(1024) unsigned char g_wt[64 * 32768];

__global__ void kan_wprep(const float* __restrict__ w) {
    const int i = blockIdx.x;
    const int o = threadIdx.x;
    const float* pc = w + ((size_t)(0 * 256 + o) * 64 + i) * 32;
    const float* ps = w + ((size_t)(1 * 256 + o) * 64 + i) * 32;
    unsigned char* dst = g_wt + (size_t)i * 32768 + (o >> 7) * 16384;
    const uint32_t rowb = (uint32_t)(o & 127) * 128;

    #pragma unroll
    for (int half = 0; half < 2; ++half) {
        const float* src = half ? ps : pc;
        #pragma unroll
        for (int g = 0; g < 4; ++g) {
            float4 v0 = *(const float4*)(src + g * 8);
            float4 v1 = *(const float4*)(src + g * 8 + 4);
            uint32_t h[4];
            h[0] = pack_f16(v0.x, v0.y); h[1] = pack_f16(v0.z, v0.w);
            h[2] = pack_f16(v1.x, v1.y); h[3] = pack_f16(v1.z, v1.w);
            uint32_t off = swz(rowb + half * 64 + g * 16);
            *(uint4*)(dst + off) = make_uint4(h[0], h[1], h[2], h[3]);
        }
    }
}

// ---------- main kernel ----------
// SMEM (64KB): A buf b @ b*16384; W buf b @ 32768 + b*16384
#define SA(b)    ((uint32_t)(b) * 16384u)
#define SW(b)    (32768u + (uint32_t)(b) * 16384u)
#define SMEM_SZ  65536

__global__ __launch_bounds__(384, 1)
void kan_mma(const float* __restrict__ x, const float* __restrict__ bias,
             float* __restrict__ out) {
    extern __shared__ __align__(1024) unsigned char sm[];
    const uint32_t sb = smem_u32(sm);
    const int t = threadIdx.x, lane = t & 31, wid = t >> 5;
    const int row0 = blockIdx.x * 128, col0 = blockIdx.y * 128;

    if (wid >= 8) {
        // ============ PRODUCERS (warps 8-11, 128 threads; 1 row each) ============
        const int ar = t - 256;                    // row 0..127
        const uint32_t genrow = (uint32_t)ar * 128;
        const uint32_t genxm  = ((uint32_t)ar & 7) << 4;
        const unsigned char* wslab = g_wt + (size_t)(col0 >> 7) * 16384;
        const float* xrow = x + (size_t)(row0 + ar) * INDIM;

        #pragma unroll 1
        for (int i = 0; i < INDIM; ++i) {
            const int b = i & 1;
            if (i >= 2) BAR_SYNC(3 + b);           // consumers freed bufs b

            // W(i) -> SW(b): 16KB over 128 threads = 8 x 16B each
            {
                const unsigned char* ws = wslab + (size_t)i * 32768;
                const uint32_t wd = sb + SW(b);
                #pragma unroll
                for (int j = 0; j < 8; ++j) {
                    uint32_t off = (uint32_t)ar * 16u + j * 2048u;
                    cpa16(wd + off, ws + off);
                }
                CP_COMMIT();
            }

            // A(i): full row, k = 1..32 cos+sin
            float xv = __ldg(xrow + i);
            float c1, s1;
            __sincosf(xv, &s1, &c1);
            float ck = c1, sk = s1;
            uint32_t chv[16], shv[16];
            #pragma unroll
            for (int p = 0; p < 16; ++p) {
                float c0 = ck, s0 = sk;
                float cA = fmaf(ck, c1, -(sk * s1));   // k = 2p+2
                float sA = fmaf(sk, c1, ck * s1);
                chv[p] = pack_f16(c0, cA);
                shv[p] = pack_f16(s0, sA);
                ck = fmaf(cA, c1, -(sA * s1));         // k = 2p+3
                sk = fmaf(sA, c1, cA * s1);
            }
            const uint32_t ab = SA(b);
            #pragma unroll
            for (int g = 0; g < 4; ++g) {
                uint32_t cb = g * 16;
                uint32_t oc = genrow + (cb ^ genxm);          // cos cols
                uint32_t os = genrow + ((cb + 64u) ^ genxm);  // sin cols
                *(uint4*)(sm + ab + oc) = make_uint4(chv[4*g], chv[4*g+1], chv[4*g+2], chv[4*g+3]);
                *(uint4*)(sm + ab + os) = make_uint4(shv[4*g], shv[4*g+1], shv[4*g+2], shv[4*g+3]);
            }

            CP_WAIT0();                             // W(i) landed (this thread)
            BAR_ARRIVE(1 + b);                      // publish FULL(b)
        }
        return;
    }

    // ================= CONSUMERS (warps 0-7) =================
    const int wm = wid & 3, wn = wid >> 2;          // 4 x 2 warp grid
    const int m0 = wm * 32, n0 = wn * 64;
    const int a_r   = m0 + (lane & 15);
    const uint32_t a_kadd = (lane & 16) ? 16u : 0u;
    const uint32_t a_xm   = ((uint32_t)a_r & 7) << 4;
    const int b_r   = n0 + (lane & 7) + ((lane & 16) ? 8 : 0);
    const uint32_t b_kadd = (lane & 8) ? 16u : 0u;
    const uint32_t b_xm   = ((uint32_t)b_r & 7) << 4;

    float acc[2][8][4];
    #pragma unroll
    for (int mt = 0; mt < 2; ++mt)
        #pragma unroll
        for (int nt = 0; nt < 8; ++nt)
            #pragma unroll
            for (int e = 0; e < 4; ++e) acc[mt][nt][e] = 0.0f;

    uint32_t af[2][2][4];   // [buf][mt][4]
    uint32_t bf[2][4][4];   // [buf][pr][4]

    #define LOAD_FRAGS(ks, buf, Ab, Wb) do {                                    \
        const uint32_t kb_ = (uint32_t)(ks) * 32;                               \
        const uint32_t ac_ = (kb_ + a_kadd) ^ a_xm;                             \
        const uint32_t bc_ = (kb_ + b_kadd) ^ b_xm;                             \
        _Pragma("unroll")                                                       \
        for (int mt = 0; mt < 2; ++mt)                                          \
            ldsm4(af[buf][mt], (Ab) + (uint32_t)(a_r + mt * 16) * 128 + ac_);   \
        _Pragma("unroll")                                                       \
        for (int pr = 0; pr < 4; ++pr)                                          \
            ldsm4(bf[buf][pr], (Wb) + (uint32_t)(b_r + pr * 16) * 128 + bc_);   \
    } while (0)

    #define DO_MMAS(buf) do {                                                   \
        _Pragma("unroll")                                                       \
        for (int pr = 0; pr < 4; ++pr)                                          \
            _Pragma("unroll")                                                   \
            for (int mt = 0; mt < 2; ++mt)                                      \
                _Pragma("unroll")                                               \
                for (int h = 0; h < 2; ++h)                                     \
                    mma_f16(acc[mt][pr * 2 + h], af[buf][mt],                   \
                            bf[buf][pr][h * 2], bf[buf][pr][h * 2 + 1]);        \
    } while (0)

    #pragma unroll 1
    for (int i = 0; i < INDIM; ++i) {
        const int b = i & 1;
        BAR_SYNC(1 + b);                            // wait FULL(b)
        const uint32_t Ab = sb + SA(b);
        const uint32_t Wb = sb + SW(b);
        LOAD_FRAGS(0, 0, Ab, Wb);
        #pragma unroll
        for (int ks = 0; ks < 4; ++ks) {
            const int cur = ks & 1;
            if (ks < 3) LOAD_FRAGS(ks + 1, cur ^ 1, Ab, Wb);
            DO_MMAS(cur);
        }
        BAR_ARRIVE(3 + b);                          // release EMPTY(b)
    }
    #undef LOAD_FRAGS
    #undef DO_MMAS

    // ---------- epilogue ----------
    const int grp = lane >> 2, tig = lane & 3;
    #pragma unroll
    for (int nt = 0; nt < 8; ++nt) {
        const int cg = col0 + n0 + nt * 8 + 2 * tig;
        const float2 bs = *(const float2*)&bias[cg];
        #pragma unroll
        for (int mt = 0; mt < 2; ++mt) {
            const int rg = row0 + m0 + mt * 16 + grp;
            float2 v0 = make_float2(acc[mt][nt][0] + bs.x, acc[mt][nt][1] + bs.y);
            float2 v1 = make_float2(acc[mt][nt][2] + bs.x, acc[mt][nt][3] + bs.y);
            *(float2*)&out[(size_t)rg * OUTDIM + cg]       = v0;
            *(float2*)&out[(size_t)(rg + 8) * OUTDIM + cg] = v1;
        }
    }
}

extern "C" void kernel_launch(void* const* d_in, const int* in_sizes, int n_in,
                              void* d_out, int out_size) {
    const float* x    = (const float*)d_in[0];   // [32768][64]
    const float* w    = (const float*)d_in[1];   // [2][256][64][32]
    const float* bias = (const float*)d_in[2];   // [1][256]
    float* out        = (float*)d_out;           // [32768][256]

    cudaFuncSetAttribute(kan_mma, cudaFuncAttributeMaxDynamicSharedMemorySize, SMEM_SZ);

    kan_wprep<<<64, 256>>>(w);
    dim3 grid(NROWS / 128, OUTDIM / 128);        // (256, 2)
    kan_mma<<<grid, 384, SMEM_SZ>>>(x, bias, out);
}

// round 12
// speedup vs baseline: 1.3211x; 1.0978x over previous
#include <cuda_runtime.h>
#include <cstdint>
#include <math.h>

// NaiveFourierKANLayer, warp-specialized fp16 MMA, K=128 pipeline stages:
//   y[32768,256] = A[32768,4096] @ W[4096,256] + bias
// 384 threads/CTA: warps 0-7 consumers (LDSM+HMMA, double-buffered fragments),
// warps 8-11 producers (full-row A-gen + W cp.async).
// Each stage carries TWO input dims (128 features) -> half the barrier rate,
// 2x longer uninterrupted MMA runs. 2 stages x (32KB A + 32KB W) = 128KB smem.

#define NROWS   32768
#define INDIM   64
#define OUTDIM  256

// ---------- helpers ----------
__device__ __forceinline__ uint32_t smem_u32(const void* p) {
    uint32_t a;
    asm("{ .reg .u64 t; cvta.to.shared.u64 t, %1; cvt.u32.u64 %0, t; }" : "=r"(a) : "l"(p));
    return a;
}
__device__ __forceinline__ uint32_t pack_f16(float e0, float e1) {   // low half = e0
    uint32_t r;
    asm("cvt.rn.f16x2.f32 %0, %1, %2;" : "=r"(r) : "f"(e1), "f"(e0));
    return r;
}
__device__ __forceinline__ uint32_t swz(uint32_t off) { return off ^ ((off >> 3) & 0x70); }

__device__ __forceinline__ void cpa16(uint32_t dst, const void* src) {
    asm volatile("cp.async.cg.shared.global [%0], [%1], 16;" :: "r"(dst), "l"(src) : "memory");
}
#define CP_COMMIT() asm volatile("cp.async.commit_group;" ::: "memory")
#define CP_WAIT0()  asm volatile("cp.async.wait_group 0;" ::: "memory")

// named split barriers, whole-CTA count (384)
#define BAR_SYNC(id)   asm volatile("bar.sync %0, 384;"   :: "r"(id) : "memory")
#define BAR_ARRIVE(id) asm volatile("bar.arrive %0, 384;" :: "r"(id) : "memory")
// FULL[s] = 1+s (producers arrive, consumers sync), s = stage&1
// EMPTY[s] = 3+s (consumers arrive, producers sync)

__device__ __forceinline__ void ldsm4(uint32_t* r, uint32_t addr) {
    asm volatile("ldmatrix.sync.aligned.m8n8.x4.shared.b16 {%0,%1,%2,%3}, [%4];"
                 : "=r"(r[0]), "=r"(r[1]), "=r"(r[2]), "=r"(r[3]) : "r"(addr));
}
__device__ __forceinline__ void mma_f16(float* d, const uint32_t* a, uint32_t b0, uint32_t b1) {
    asm volatile("mma.sync.aligned.m16n8k16.row.col.f32.f16.f16.f32 "
                 "{%0,%1,%2,%3},{%4,%5,%6,%7},{%8,%9},{%0,%1,%2,%3};"
                 : "+f"(d[0]), "+f"(d[1]), "+f"(d[2]), "+f"(d[3])
                 : "r"(a[0]), "r"(a[1]), "r"(a[2]), "r"(a[3]), "r"(b0), "r"(b1));
}

// ---------- pre-swizzled fp16 W tiles ----------
// g_wt[i][slab(o>>7)][ swz((o&127)*128 + f*2) ] : 32KB per i (2 slabs x 16KB)
__device__ __align__(1024) unsigned char g_wt[64 * 32768];

__global__ void kan_wprep(const float* __restrict__ w) {
    const int i = blockIdx.x;
    const int o = threadIdx.x;
    const float* pc = w + ((size_t)(0 * 256 + o) * 64 + i) * 32;
    const float* ps = w + ((size_t)(1 * 256 + o) * 64 + i) * 32;
    unsigned char* dst = g_wt + (size_t)i * 32768 + (o >> 7) * 16384;
    const uint32_t rowb = (uint32_t)(o & 127) * 128;

    #pragma unroll
    for (int half = 0; half < 2; ++half) {
        const float* src = half ? ps : pc;
        #pragma unroll
        for (int g = 0; g < 4; ++g) {
            float4 v0 = *(const float4*)(src + g * 8);
            float4 v1 = *(const float4*)(src + g * 8 + 4);
            uint32_t h[4];
            h[0] = pack_f16(v0.x, v0.y); h[1] = pack_f16(v0.z, v0.w);
            h[2] = pack_f16(v1.x, v1.y); h[3] = pack_f16(v1.z, v1.w);
            uint32_t off = swz(rowb + half * 64 + g * 16);
            *(uint4*)(dst + off) = make_uint4(h[0], h[1], h[2], h[3]);
        }
    }
}

// ---------- main kernel ----------
// SMEM (128KB): stage s (s=0,1):
//   A: SA(s) + d*16384  (d = dim within stage)     0 .. 64KB
//   W: SW(s) + d*16384                             64 .. 128KB
#define SA(s)    ((uint32_t)(s) * 32768u)
#define SW(s)    (65536u + (uint32_t)(s) * 32768u)
#define SMEM_SZ  131072

__global__ __launch_bounds__(384, 1)
void kan_mma(const float* __restrict__ x, const float* __restrict__ bias,
             float* __restrict__ out) {
    extern __shared__ __align__(1024) unsigned char sm[];
    const uint32_t sb = smem_u32(sm);
    const int t = threadIdx.x, lane = t & 31, wid = t >> 5;
    const int row0 = blockIdx.x * 128, col0 = blockIdx.y * 128;

    if (wid >= 8) {
        // ============ PRODUCERS (warps 8-11, 128 threads; 1 row each) ============
        const int ar = t - 256;                    // row 0..127
        const uint32_t genrow = (uint32_t)ar * 128;
        const uint32_t genxm  = ((uint32_t)ar & 7) << 4;
        const unsigned char* wslab = g_wt + (size_t)(col0 >> 7) * 16384;
        const float* xrow = x + (size_t)(row0 + ar) * INDIM;

        #pragma unroll 1
        for (int j = 0; j < INDIM / 2; ++j) {      // stage j covers dims 2j, 2j+1
            const int s = j & 1;
            if (j >= 2) BAR_SYNC(3 + s);           // consumers freed stage s

            // W(2j), W(2j+1) -> SW(s): 32KB over 128 threads = 16 x 16B each
            {
                const unsigned char* ws = wslab + (size_t)(2 * j) * 32768;
                const uint32_t wd = sb + SW(s);
                #pragma unroll
                for (int d = 0; d < 2; ++d)
                    #pragma unroll
                    for (int q = 0; q < 8; ++q) {
                        uint32_t off = (uint32_t)ar * 16u + q * 2048u;
                        cpa16(wd + d * 16384u + off, ws + (size_t)d * 32768 + off);
                    }
                CP_COMMIT();
            }

            // A rows for dims 2j (d=0) and 2j+1 (d=1)
            const float2 xv2 = __ldg((const float2*)(xrow + 2 * j));
            #pragma unroll
            for (int d = 0; d < 2; ++d) {
                const float xv = d ? xv2.y : xv2.x;
                float c1, s1;
                __sincosf(xv, &s1, &c1);
                float ck = c1, sk = s1;
                uint32_t chv[16], shv[16];
                #pragma unroll
                for (int p = 0; p < 16; ++p) {
                    float c0 = ck, s0 = sk;
                    float cA = fmaf(ck, c1, -(sk * s1));   // k = 2p+2
                    float sA = fmaf(sk, c1, ck * s1);
                    chv[p] = pack_f16(c0, cA);
                    shv[p] = pack_f16(s0, sA);
                    ck = fmaf(cA, c1, -(sA * s1));         // k = 2p+3
                    sk = fmaf(sA, c1, cA * s1);
                }
                const uint32_t ab = SA(s) + (uint32_t)d * 16384u;
                #pragma unroll
                for (int g = 0; g < 4; ++g) {
                    uint32_t cb = g * 16;
                    uint32_t oc = genrow + (cb ^ genxm);          // cos cols
                    uint32_t os = genrow + ((cb + 64u) ^ genxm);  // sin cols
                    *(uint4*)(sm + ab + oc) = make_uint4(chv[4*g], chv[4*g+1], chv[4*g+2], chv[4*g+3]);
                    *(uint4*)(sm + ab + os) = make_uint4(shv[4*g], shv[4*g+1], shv[4*g+2], shv[4*g+3]);
                }
            }

            CP_WAIT0();                            // W landed (this thread's chunks)
            BAR_ARRIVE(1 + s);                     // publish FULL(s)
        }
        return;
    }

    // ================= CONSUMERS (warps 0-7) =================
    const int wm = wid & 3, wn = wid >> 2;          // 4 x 2 warp grid
    const int m0 = wm * 32, n0 = wn * 64;
    const int a_r   = m0 + (lane & 15);
    const uint32_t a_kadd = (lane & 16) ? 16u : 0u;
    const uint32_t a_xm   = ((uint32_t)a_r & 7) << 4;
    const int b_r   = n0 + (lane & 7) + ((lane & 16) ? 8 : 0);
    const uint32_t b_kadd = (lane & 8) ? 16u : 0u;
    const uint32_t b_xm   = ((uint32_t)b_r & 7) << 4;

    float acc[2][8][4];
    #pragma unroll
    for (int mt = 0; mt < 2; ++mt)
        #pragma unroll
        for (int nt = 0; nt < 8; ++nt)
            #pragma unroll
            for (int e = 0; e < 4; ++e) acc[mt][nt][e] = 0.0f;

    uint32_t af[2][2][4];   // [buf][mt][4]
    uint32_t bf[2][4][4];   // [buf][pr][4]

    // ks2 in [0,8): d = ks2>>2 selects the 16KB sub-tile, ksl = ks2&3 the K chunk
    #define LOAD_FRAGS(ks2, buf, Abase, Wbase) do {                             \
        const uint32_t d_  = (uint32_t)(ks2) >> 2;                              \
        const uint32_t kb_ = ((uint32_t)(ks2) & 3) * 32;                        \
        const uint32_t Ab_ = (Abase) + d_ * 16384u;                             \
        const uint32_t Wb_ = (Wbase) + d_ * 16384u;                             \
        const uint32_t ac_ = (kb_ + a_kadd) ^ a_xm;                             \
        const uint32_t bc_ = (kb_ + b_kadd) ^ b_xm;                             \
        _Pragma("unroll")                                                       \
        for (int mt = 0; mt < 2; ++mt)                                          \
            ldsm4(af[buf][mt], Ab_ + (uint32_t)(a_r + mt * 16) * 128 + ac_);    \
        _Pragma("unroll")                                                       \
        for (int pr = 0; pr < 4; ++pr)                                          \
            ldsm4(bf[buf][pr], Wb_ + (uint32_t)(b_r + pr * 16) * 128 + bc_);    \
    } while (0)

    #define DO_MMAS(buf) do {                                                   \
        _Pragma("unroll")                                                       \
        for (int pr = 0; pr < 4; ++pr)                                          \
            _Pragma("unroll")                                                   \
            for (int mt = 0; mt < 2; ++mt)                                      \
                _Pragma("unroll")                                               \
                for (int h = 0; h < 2; ++h)                                     \
                    mma_f16(acc[mt][pr * 2 + h], af[buf][mt],                   \
                            bf[buf][pr][h * 2], bf[buf][pr][h * 2 + 1]);        \
    } while (0)

    #pragma unroll 1
    for (int j = 0; j < INDIM / 2; ++j) {
        const int s = j & 1;
        BAR_SYNC(1 + s);                            // wait FULL(s)
        const uint32_t Ab = sb + SA(s);
        const uint32_t Wb = sb + SW(s);
        LOAD_FRAGS(0, 0, Ab, Wb);
        #pragma unroll
        for (int ks2 = 0; ks2 < 8; ++ks2) {
            const int cur = ks2 & 1;
            if (ks2 < 7) LOAD_FRAGS(ks2 + 1, cur ^ 1, Ab, Wb);
            DO_MMAS(cur);
        }
        BAR_ARRIVE(3 + s);                          // release EMPTY(s)
    }
    #undef LOAD_FRAGS
    #undef DO_MMAS

    // ---------- epilogue ----------
    const int grp = lane >> 2, tig = lane & 3;
    #pragma unroll
    for (int nt = 0; nt < 8; ++nt) {
        const int cg = col0 + n0 + nt * 8 + 2 * tig;
        const float2 bs = *(const float2*)&bias[cg];
        #pragma unroll
        for (int mt = 0; mt < 2; ++mt) {
            const int rg = row0 + m0 + mt * 16 + grp;
            float2 v0 = make_float2(acc[mt][nt][0] + bs.x, acc[mt][nt][1] + bs.y);
            float2 v1 = make_float2(acc[mt][nt][2] + bs.x, acc[mt][nt][3] + bs.y);
            *(float2*)&out[(size_t)rg * OUTDIM + cg]       = v0;
            *(float2*)&out[(size_t)(rg + 8) * OUTDIM + cg] = v1;
        }
    }
}

extern "C" void kernel_launch(void* const* d_in, const int* in_sizes, int n_in,
                              void* d_out, int out_size) {
    const float* x    = (const float*)d_in[0];   // [32768][64]
    const float* w    = (const float*)d_in[1];   // [2][256][64][32]
    const float* bias = (const float*)d_in[2];   // [1][256]
    float* out        = (float*)d_out;           // [32768][256]

    cudaFuncSetAttribute(kan_mma, cudaFuncAttributeMaxDynamicSharedMemorySize, SMEM_SZ);

    kan_wprep<<<64, 256>>>(w);
    dim3 grid(NROWS / 128, OUTDIM / 128);        // (256, 2)
    kan_mma<<<grid, 384, SMEM_SZ>>>(x, bias, out);
}